// round 3
// baseline (speedup 1.0000x reference)
#include <cuda_runtime.h>
#include <cuda_bf16.h>

#define D   128
#define H   4
#define MAX_ENT 100000
#define MAX_E   400000

// ---------------- scratch (__device__ globals; no allocation allowed) ----------------
__device__ float g_Q[(size_t)MAX_ENT * D];      // entity_emb @ qTrans
__device__ float g_S[(size_t)MAX_ENT * D];      // phase-A accumulator -> kg_emb (in place)
__device__ float g_normA[(size_t)MAX_ENT * H];  // per-(entity,head) sum of exp(att)
__device__ float g_w[(size_t)MAX_E];            // per-edge scalar attention logit (phase B)
__device__ int   g_m[(size_t)MAX_ENT];          // per-entity max(w) as float bits (w >= 0)
__device__ float g_ssum[(size_t)MAX_ENT];       // per-entity softmax denominator

// ---------------------------------------------------------------------------
// Kernel 1: Q_all = entity_emb @ qTrans   (qT in SMEM, 4 rows per warp-iter)
// ---------------------------------------------------------------------------
__global__ __launch_bounds__(256) void gemm_q_kernel(const float* __restrict__ ent,
                                                     const float* __restrict__ qT,
                                                     int n_ent) {
    extern __shared__ float sm[];
    float* qT_s = sm;                 // D*D floats
    float* u_s  = sm + D * D;         // nwarps*4*D floats
    int tid = threadIdx.x, lane = tid & 31, wid = tid >> 5;
    int nw = blockDim.x >> 5;

    for (int i = tid * 4; i < D * D; i += blockDim.x * 4)
        *(float4*)&qT_s[i] = *(const float4*)&qT[i];
    __syncthreads();

    float* u = u_s + wid * 4 * D;
    int gw  = blockIdx.x * nw + wid;
    int tot = gridDim.x * nw;

    for (int g = gw; g * 4 < n_ent; g += tot) {
        int r0 = g * 4;
        int n  = min(4, n_ent - r0);
        #pragma unroll
        for (int e = 0; e < 4; e++) {
            float4 tv = make_float4(0.f, 0.f, 0.f, 0.f);
            if (e < n) tv = *(const float4*)&ent[(size_t)(r0 + e) * D + lane * 4];
            *(float4*)&u[e * D + lane * 4] = tv;
        }
        __syncwarp();

        float a0[4] = {0,0,0,0}, a1[4] = {0,0,0,0}, a2[4] = {0,0,0,0}, a3[4] = {0,0,0,0};
        #pragma unroll 4
        for (int i = 0; i < D; i++) {
            float4 qv = *(float4*)&qT_s[i * D + lane * 4];
            #pragma unroll
            for (int e = 0; e < 4; e++) {
                float ue = u[e * D + i];
                a0[e] = fmaf(ue, qv.x, a0[e]);
                a1[e] = fmaf(ue, qv.y, a1[e]);
                a2[e] = fmaf(ue, qv.z, a2[e]);
                a3[e] = fmaf(ue, qv.w, a3[e]);
            }
        }
        #pragma unroll
        for (int e = 0; e < 4; e++) {
            if (e < n)
                *(float4*)&g_Q[(size_t)(r0 + e) * D + lane * 4] =
                    make_float4(a0[e], a1[e], a2[e], a3[e]);
        }
        __syncwarp();
    }
}

// ---------------------------------------------------------------------------
// Kernel 2 (dominant): per-edge  u = ent[tail]*rel;  k = u@kT; v = u@vT;
//   att[h4] = clip(Q[head]·k per head, -10, 10); ea = exp(att)
//   atomically accumulate  S[head] += ea*v,  normA[head,h4] += ea
// kT,vT resident in SMEM (128 KB); 4 edges per warp iteration (register tiled)
// ---------------------------------------------------------------------------
__global__ __launch_bounds__(256) void edge_phaseA_kernel(const float* __restrict__ ent,
                                                          const float* __restrict__ weight,
                                                          const float* __restrict__ kT,
                                                          const float* __restrict__ vT,
                                                          const int* __restrict__ head,
                                                          const int* __restrict__ tail,
                                                          const int* __restrict__ etype,
                                                          int E) {
    extern __shared__ float sm[];
    float* kT_s = sm;                  // D*D
    float* vT_s = sm + D * D;          // D*D
    float* u_s  = sm + 2 * D * D;      // nwarps*4*D
    int tid = threadIdx.x, lane = tid & 31, wid = tid >> 5;
    int nw = blockDim.x >> 5;

    for (int i = tid * 4; i < 2 * D * D; i += blockDim.x * 4) {
        if (i < D * D) *(float4*)&sm[i] = *(const float4*)&kT[i];
        else           *(float4*)&sm[i] = *(const float4*)&vT[i - D * D];
    }
    __syncthreads();

    float* u = u_s + wid * 4 * D;
    int gw  = blockIdx.x * nw + wid;
    int tot = gridDim.x * nw;

    for (int g = gw; g * 4 < E; g += tot) {
        int e0 = g * 4;
        int n  = min(4, E - e0);
        int hidx[4];

        #pragma unroll
        for (int e = 0; e < 4; e++) {
            float4 uv = make_float4(0.f, 0.f, 0.f, 0.f);
            if (e < n) {
                int t = tail[e0 + e];
                int r = etype[e0 + e] - 1;
                hidx[e] = head[e0 + e];
                float4 tv = *(const float4*)&ent[(size_t)t * D + lane * 4];
                float4 rv = *(const float4*)&weight[(size_t)r * D + lane * 4];
                uv = make_float4(tv.x * rv.x, tv.y * rv.y, tv.z * rv.z, tv.w * rv.w);
            }
            *(float4*)&u[e * D + lane * 4] = uv;
        }
        __syncwarp();

        float k0[4] = {0,0,0,0}, k1[4] = {0,0,0,0}, k2[4] = {0,0,0,0}, k3[4] = {0,0,0,0};
        float v0[4] = {0,0,0,0}, v1[4] = {0,0,0,0}, v2[4] = {0,0,0,0}, v3[4] = {0,0,0,0};

        #pragma unroll 4
        for (int i = 0; i < D; i++) {
            float4 kv = *(float4*)&kT_s[i * D + lane * 4];
            float4 vv = *(float4*)&vT_s[i * D + lane * 4];
            #pragma unroll
            for (int e = 0; e < 4; e++) {
                float ue = u[e * D + i];
                k0[e] = fmaf(ue, kv.x, k0[e]);
                k1[e] = fmaf(ue, kv.y, k1[e]);
                k2[e] = fmaf(ue, kv.z, k2[e]);
                k3[e] = fmaf(ue, kv.w, k3[e]);
                v0[e] = fmaf(ue, vv.x, v0[e]);
                v1[e] = fmaf(ue, vv.y, v1[e]);
                v2[e] = fmaf(ue, vv.z, v2[e]);
                v3[e] = fmaf(ue, vv.w, v3[e]);
            }
        }

        #pragma unroll
        for (int e = 0; e < 4; e++) {
            if (e >= n) break;
            int h = hidx[e];
            float4 qv = *(const float4*)&g_Q[(size_t)h * D + lane * 4];
            float p = qv.x * k0[e] + qv.y * k1[e] + qv.z * k2[e] + qv.w * k3[e];
            // lanes 8*hh .. 8*hh+7 jointly own head slice hh = lane/8 (32 columns)
            p += __shfl_xor_sync(0xffffffffu, p, 1);
            p += __shfl_xor_sync(0xffffffffu, p, 2);
            p += __shfl_xor_sync(0xffffffffu, p, 4);
            float att = fminf(fmaxf(p, -10.f), 10.f);
            float ea  = __expf(att);
            float* Sr = &g_S[(size_t)h * D + lane * 4];
            atomicAdd(Sr + 0, ea * v0[e]);
            atomicAdd(Sr + 1, ea * v1[e]);
            atomicAdd(Sr + 2, ea * v2[e]);
            atomicAdd(Sr + 3, ea * v3[e]);
            if ((lane & 7) == 0)
                atomicAdd(&g_normA[(size_t)h * H + (lane >> 3)], ea);
        }
        __syncwarp();
    }
}

// ---------------------------------------------------------------------------
// Kernel 3: kg_emb = S / (normA + 1e-8)  (in place in g_S)
// ---------------------------------------------------------------------------
__global__ __launch_bounds__(256) void finalize_kg_kernel(int n_ent) {
    int idx = blockIdx.x * blockDim.x + threadIdx.x;   // over n_ent * 32 (float4 each)
    if (idx >= n_ent * (D / 4)) return;
    int row = idx >> 5;
    int q   = idx & 31;                                 // float4 index within row
    float inv = 1.f / (g_normA[(size_t)row * H + (q >> 3)] + 1e-8f);
    float4 s = *(float4*)&g_S[(size_t)idx * 4];
    s.x *= inv; s.y *= inv; s.z *= inv; s.w *= inv;
    *(float4*)&g_S[(size_t)idx * 4] = s;
}

// ---------------------------------------------------------------------------
// Kernel 4: per-edge w = (||kg[h]*rel|| * ||kg[t]*rel||)^2 = sumsq_h * sumsq_t
//           segment max via int-atomicMax (w >= 0). One warp per edge.
// ---------------------------------------------------------------------------
__global__ __launch_bounds__(256) void edge_w_kernel(const float* __restrict__ weight,
                                                     const int* __restrict__ head,
                                                     const int* __restrict__ tail,
                                                     const int* __restrict__ etype,
                                                     int E) {
    int lane = threadIdx.x & 31;
    int gw   = (blockIdx.x * blockDim.x + threadIdx.x) >> 5;
    int tot  = (gridDim.x * blockDim.x) >> 5;
    for (int e = gw; e < E; e += tot) {
        int h = head[e], t = tail[e], r = etype[e] - 1;
        float4 rv = *(const float4*)&weight[(size_t)r * D + lane * 4];
        float4 hv = *(const float4*)&g_S[(size_t)h * D + lane * 4];
        float4 tv = *(const float4*)&g_S[(size_t)t * D + lane * 4];
        float ph = 0.f, pt = 0.f;
        float x;
        x = hv.x * rv.x; ph = fmaf(x, x, ph);
        x = hv.y * rv.y; ph = fmaf(x, x, ph);
        x = hv.z * rv.z; ph = fmaf(x, x, ph);
        x = hv.w * rv.w; ph = fmaf(x, x, ph);
        x = tv.x * rv.x; pt = fmaf(x, x, pt);
        x = tv.y * rv.y; pt = fmaf(x, x, pt);
        x = tv.z * rv.z; pt = fmaf(x, x, pt);
        x = tv.w * rv.w; pt = fmaf(x, x, pt);
        #pragma unroll
        for (int off = 16; off > 0; off >>= 1) {
            ph += __shfl_xor_sync(0xffffffffu, ph, off);
            pt += __shfl_xor_sync(0xffffffffu, pt, off);
        }
        float w = ph * pt;   // >= 0
        if (lane == 0) {
            g_w[e] = w;
            atomicMax(&g_m[h], __float_as_int(w));
        }
    }
}

// ---------------------------------------------------------------------------
// Kernel 5: e = exp(w - m[h]);  out[h] += e * ent[tail];  ssum[h] += e
// ---------------------------------------------------------------------------
__global__ __launch_bounds__(256) void edge_soft_kernel(const float* __restrict__ ent,
                                                        const int* __restrict__ head,
                                                        const int* __restrict__ tail,
                                                        int E,
                                                        float* __restrict__ out) {
    int lane = threadIdx.x & 31;
    int gw   = (blockIdx.x * blockDim.x + threadIdx.x) >> 5;
    int tot  = (gridDim.x * blockDim.x) >> 5;
    for (int e = gw; e < E; e += tot) {
        int h = head[e], t = tail[e];
        float m  = __int_as_float(g_m[h]);
        float ex = __expf(g_w[e] - m);
        float4 tv = *(const float4*)&ent[(size_t)t * D + lane * 4];
        float* o = &out[(size_t)h * D + lane * 4];
        atomicAdd(o + 0, ex * tv.x);
        atomicAdd(o + 1, ex * tv.y);
        atomicAdd(o + 2, ex * tv.z);
        atomicAdd(o + 3, ex * tv.w);
        if (lane == 0) atomicAdd(&g_ssum[h], ex);
    }
}

// ---------------------------------------------------------------------------
// Kernel 6: out /= ssum (rows with no edges stay 0)
// ---------------------------------------------------------------------------
__global__ __launch_bounds__(256) void finalize_out_kernel(float* __restrict__ out, int n_ent) {
    int idx = blockIdx.x * blockDim.x + threadIdx.x;   // over n_ent * 32 (float4 each)
    if (idx >= n_ent * (D / 4)) return;
    int row = idx >> 5;
    float s = g_ssum[row];
    float inv = (s > 0.f) ? (1.f / s) : 0.f;
    float4 o = *(float4*)&out[(size_t)idx * 4];
    o.x *= inv; o.y *= inv; o.z *= inv; o.w *= inv;
    *(float4*)&out[(size_t)idx * 4] = o;
}

// ---------------------------------------------------------------------------
extern "C" void kernel_launch(void* const* d_in, const int* in_sizes, int n_in,
                              void* d_out, int out_size) {
    const float* ent    = (const float*)d_in[0];   // [n_ent, 128]
    const float* weight = (const float*)d_in[3];   // [32, 128]
    const float* qT     = (const float*)d_in[4];   // [128, 128]
    const float* kT     = (const float*)d_in[5];
    const float* vT     = (const float*)d_in[6];
    const int*   eidx   = (const int*)d_in[7];     // [2, E]
    const int*   etype  = (const int*)d_in[8];     // [E]

    int E     = in_sizes[8];
    int n_ent = in_sizes[0] / D;
    const int* head = eidx;
    const int* tail = eidx + E;
    float* out = (float*)d_out;

    void *pS, *pN, *pM, *pSs;
    cudaGetSymbolAddress(&pS,  g_S);
    cudaGetSymbolAddress(&pN,  g_normA);
    cudaGetSymbolAddress(&pM,  g_m);
    cudaGetSymbolAddress(&pSs, g_ssum);
    cudaMemsetAsync(pS,  0, (size_t)n_ent * D * sizeof(float));
    cudaMemsetAsync(pN,  0, (size_t)n_ent * H * sizeof(float));
    cudaMemsetAsync(pM,  0, (size_t)n_ent * sizeof(int));
    cudaMemsetAsync(pSs, 0, (size_t)n_ent * sizeof(float));
    cudaMemsetAsync(d_out, 0, (size_t)out_size * sizeof(float));

    // Kernel 1: Q_all
    int smem_q = (D * D + 8 * 4 * D) * (int)sizeof(float);   // 80 KB
    cudaFuncSetAttribute(gemm_q_kernel, cudaFuncAttributeMaxDynamicSharedMemorySize, smem_q);
    gemm_q_kernel<<<148, 256, smem_q>>>(ent, qT, n_ent);

    // Kernel 2: edge phase A (dominant)
    int smem_e = (2 * D * D + 8 * 4 * D) * (int)sizeof(float);  // 144 KB
    cudaFuncSetAttribute(edge_phaseA_kernel, cudaFuncAttributeMaxDynamicSharedMemorySize, smem_e);
    edge_phaseA_kernel<<<148, 256, smem_e>>>(ent, weight, kT, vT, head, tail, etype, E);

    // Kernel 3
    int n3 = n_ent * (D / 4);
    finalize_kg_kernel<<<(n3 + 255) / 256, 256>>>(n_ent);

    // Kernel 4 / 5
    edge_w_kernel<<<2048, 256>>>(weight, head, tail, etype, E);
    edge_soft_kernel<<<2048, 256>>>(ent, head, tail, E, out);

    // Kernel 6
    finalize_out_kernel<<<(n3 + 255) / 256, 256>>>(out, n_ent);
}

// round 4
// speedup vs baseline: 2.0393x; 2.0393x over previous
#include <cuda_runtime.h>
#include <cuda_bf16.h>

#define D   128
#define H   4
#define MAX_ENT 100000
#define MAX_E   400000

typedef unsigned long long u64;

// ---------------- packed f32x2 helpers (SASS FFMA2 — only reachable via PTX) ----
__device__ __forceinline__ u64 pack2(float x) {
    u64 r; asm("mov.b64 %0, {%1, %1};" : "=l"(r) : "r"(__float_as_uint(x)));
    return r;
}
__device__ __forceinline__ void ffma2(u64 &acc, u64 a, u64 b) {
    asm("fma.rn.f32x2 %0, %1, %2, %0;" : "+l"(acc) : "l"(a), "l"(b));
}
__device__ __forceinline__ float lo2(u64 v) { return __uint_as_float((unsigned)v); }
__device__ __forceinline__ float hi2(u64 v) { return __uint_as_float((unsigned)(v >> 32)); }

__device__ __forceinline__ void red_add_v4(float* p, float a, float b, float c, float d) {
    asm volatile("red.global.add.v4.f32 [%0], {%1, %2, %3, %4};"
                 :: "l"(p), "f"(a), "f"(b), "f"(c), "f"(d) : "memory");
}

// ---------------- scratch (__device__ globals; no allocation allowed) ----------------
__device__ float g_Q[(size_t)MAX_ENT * D];      // entity_emb @ qTrans
__device__ float g_S[(size_t)MAX_ENT * D];      // phase-A accumulator -> kg_emb (in place)
__device__ float g_normA[(size_t)MAX_ENT * H];  // per-(entity,head) sum of exp(att)
__device__ float g_w[(size_t)MAX_E];            // per-edge scalar attention logit (phase B)
__device__ int   g_m[(size_t)MAX_ENT];          // per-entity max(w) as float bits (w >= 0)
__device__ float g_ssum[(size_t)MAX_ENT];       // per-entity softmax denominator

// ---------------------------------------------------------------------------
// Kernel 1: Q_all = entity_emb @ qTrans   (qT in SMEM, 4 rows per warp-iter, f32x2)
// ---------------------------------------------------------------------------
__global__ __launch_bounds__(256) void gemm_q_kernel(const float* __restrict__ ent,
                                                     const float* __restrict__ qT,
                                                     int n_ent) {
    extern __shared__ float sm[];
    float* qT_s = sm;                 // D*D floats
    float* u_s  = sm + D * D;         // nwarps*4*D floats
    int tid = threadIdx.x, lane = tid & 31, wid = tid >> 5;
    int nw = blockDim.x >> 5;

    for (int i = tid * 4; i < D * D; i += blockDim.x * 4)
        *(float4*)&qT_s[i] = *(const float4*)&qT[i];
    __syncthreads();

    float* u = u_s + wid * 4 * D;
    int gw  = blockIdx.x * nw + wid;
    int tot = gridDim.x * nw;

    for (int g = gw; g * 4 < n_ent; g += tot) {
        int r0 = g * 4;
        int n  = min(4, n_ent - r0);
        #pragma unroll
        for (int e = 0; e < 4; e++) {
            float4 tv = make_float4(0.f, 0.f, 0.f, 0.f);
            if (e < n) tv = *(const float4*)&ent[(size_t)(r0 + e) * D + lane * 4];
            *(float4*)&u[e * D + lane * 4] = tv;
        }
        __syncwarp();

        u64 a01[4] = {0,0,0,0}, a23[4] = {0,0,0,0};
        #pragma unroll 4
        for (int i = 0; i < D; i++) {
            ulonglong2 qv = *(ulonglong2*)&qT_s[i * D + lane * 4];
            #pragma unroll
            for (int e = 0; e < 4; e++) {
                u64 up = pack2(u[e * D + i]);
                ffma2(a01[e], up, qv.x);
                ffma2(a23[e], up, qv.y);
            }
        }
        #pragma unroll
        for (int e = 0; e < 4; e++) {
            if (e < n)
                *(float4*)&g_Q[(size_t)(r0 + e) * D + lane * 4] =
                    make_float4(lo2(a01[e]), hi2(a01[e]), lo2(a23[e]), hi2(a23[e]));
        }
        __syncwarp();
    }
}

// ---------------------------------------------------------------------------
// Kernel 2 (dominant): per-edge  u = ent[tail]*rel;  k = u@kT; v = u@vT;
//   att[h4] = clip(Q[head]·k per head, -10, 10); ea = exp(att)
//   atomically accumulate  S[head] += ea*v (RED.128),  normA[head,h4] += ea
// kT,vT resident in SMEM (128 KB); 4 edges per warp iteration; FFMA2 inner loop
// ---------------------------------------------------------------------------
#define PA_THREADS 384
__global__ __launch_bounds__(PA_THREADS) void edge_phaseA_kernel(const float* __restrict__ ent,
                                                          const float* __restrict__ weight,
                                                          const float* __restrict__ kT,
                                                          const float* __restrict__ vT,
                                                          const int* __restrict__ head,
                                                          const int* __restrict__ tail,
                                                          const int* __restrict__ etype,
                                                          int E) {
    extern __shared__ float sm[];
    float* kT_s = sm;                  // D*D
    float* vT_s = sm + D * D;          // D*D
    float* u_s  = sm + 2 * D * D;      // nwarps*4*D
    int tid = threadIdx.x, lane = tid & 31, wid = tid >> 5;
    int nw = blockDim.x >> 5;

    for (int i = tid * 4; i < 2 * D * D; i += blockDim.x * 4) {
        if (i < D * D) *(float4*)&sm[i] = *(const float4*)&kT[i];
        else           *(float4*)&sm[i] = *(const float4*)&vT[i - D * D];
    }
    __syncthreads();

    float* u = u_s + wid * 4 * D;
    int gw  = blockIdx.x * nw + wid;
    int tot = gridDim.x * nw;

    for (int g = gw; g * 4 < E; g += tot) {
        int e0 = g * 4;
        int n  = min(4, E - e0);
        int hidx[4];

        #pragma unroll
        for (int e = 0; e < 4; e++) {
            float4 uv = make_float4(0.f, 0.f, 0.f, 0.f);
            if (e < n) {
                int t = tail[e0 + e];
                int r = etype[e0 + e] - 1;
                hidx[e] = head[e0 + e];
                float4 tv = *(const float4*)&ent[(size_t)t * D + lane * 4];
                float4 rv = *(const float4*)&weight[(size_t)r * D + lane * 4];
                uv = make_float4(tv.x * rv.x, tv.y * rv.y, tv.z * rv.z, tv.w * rv.w);
            }
            *(float4*)&u[e * D + lane * 4] = uv;
        }
        __syncwarp();

        // packed accumulators: columns (0,1) and (2,3) per edge
        u64 k01[4] = {0,0,0,0}, k23[4] = {0,0,0,0};
        u64 v01[4] = {0,0,0,0}, v23[4] = {0,0,0,0};

        #pragma unroll 4
        for (int i = 0; i < D; i++) {
            ulonglong2 kv = *(ulonglong2*)&kT_s[i * D + lane * 4];
            ulonglong2 vv = *(ulonglong2*)&vT_s[i * D + lane * 4];
            #pragma unroll
            for (int e = 0; e < 4; e++) {
                u64 up = pack2(u[e * D + i]);
                ffma2(k01[e], up, kv.x);
                ffma2(k23[e], up, kv.y);
                ffma2(v01[e], up, vv.x);
                ffma2(v23[e], up, vv.y);
            }
        }

        #pragma unroll
        for (int e = 0; e < 4; e++) {
            if (e >= n) break;
            int h = hidx[e];
            float4 qv = *(const float4*)&g_Q[(size_t)h * D + lane * 4];
            float p = qv.x * lo2(k01[e]) + qv.y * hi2(k01[e])
                    + qv.z * lo2(k23[e]) + qv.w * hi2(k23[e]);
            // lanes 8*hh .. 8*hh+7 jointly own head slice hh = lane/8 (32 columns)
            p += __shfl_xor_sync(0xffffffffu, p, 1);
            p += __shfl_xor_sync(0xffffffffu, p, 2);
            p += __shfl_xor_sync(0xffffffffu, p, 4);
            float att = fminf(fmaxf(p, -10.f), 10.f);
            float ea  = __expf(att);
            red_add_v4(&g_S[(size_t)h * D + lane * 4],
                       ea * lo2(v01[e]), ea * hi2(v01[e]),
                       ea * lo2(v23[e]), ea * hi2(v23[e]));
            if ((lane & 7) == 0)
                atomicAdd(&g_normA[(size_t)h * H + (lane >> 3)], ea);
        }
        __syncwarp();
    }
}

// ---------------------------------------------------------------------------
// Kernel 3: kg_emb = S / (normA + 1e-8)  (in place in g_S)
// ---------------------------------------------------------------------------
__global__ __launch_bounds__(256) void finalize_kg_kernel(int n_ent) {
    int idx = blockIdx.x * blockDim.x + threadIdx.x;   // over n_ent * 32 (float4 each)
    if (idx >= n_ent * (D / 4)) return;
    int row = idx >> 5;
    int q   = idx & 31;                                 // float4 index within row
    float inv = 1.f / (g_normA[(size_t)row * H + (q >> 3)] + 1e-8f);
    float4 s = *(float4*)&g_S[(size_t)idx * 4];
    s.x *= inv; s.y *= inv; s.z *= inv; s.w *= inv;
    *(float4*)&g_S[(size_t)idx * 4] = s;
}

// ---------------------------------------------------------------------------
// Kernel 4: per-edge w = (||kg[h]*rel|| * ||kg[t]*rel||)^2 = sumsq_h * sumsq_t
//           segment max via int-atomicMax (w >= 0). One warp per edge.
// ---------------------------------------------------------------------------
__global__ __launch_bounds__(256) void edge_w_kernel(const float* __restrict__ weight,
                                                     const int* __restrict__ head,
                                                     const int* __restrict__ tail,
                                                     const int* __restrict__ etype,
                                                     int E) {
    int lane = threadIdx.x & 31;
    int gw   = (blockIdx.x * blockDim.x + threadIdx.x) >> 5;
    int tot  = (gridDim.x * blockDim.x) >> 5;
    for (int e = gw; e < E; e += tot) {
        int h = head[e], t = tail[e], r = etype[e] - 1;
        float4 rv = *(const float4*)&weight[(size_t)r * D + lane * 4];
        float4 hv = *(const float4*)&g_S[(size_t)h * D + lane * 4];
        float4 tv = *(const float4*)&g_S[(size_t)t * D + lane * 4];
        float ph = 0.f, pt = 0.f;
        float x;
        x = hv.x * rv.x; ph = fmaf(x, x, ph);
        x = hv.y * rv.y; ph = fmaf(x, x, ph);
        x = hv.z * rv.z; ph = fmaf(x, x, ph);
        x = hv.w * rv.w; ph = fmaf(x, x, ph);
        x = tv.x * rv.x; pt = fmaf(x, x, pt);
        x = tv.y * rv.y; pt = fmaf(x, x, pt);
        x = tv.z * rv.z; pt = fmaf(x, x, pt);
        x = tv.w * rv.w; pt = fmaf(x, x, pt);
        #pragma unroll
        for (int off = 16; off > 0; off >>= 1) {
            ph += __shfl_xor_sync(0xffffffffu, ph, off);
            pt += __shfl_xor_sync(0xffffffffu, pt, off);
        }
        float w = ph * pt;   // >= 0
        if (lane == 0) {
            g_w[e] = w;
            atomicMax(&g_m[h], __float_as_int(w));
        }
    }
}

// ---------------------------------------------------------------------------
// Kernel 5: e = exp(w - m[h]);  out[h] += e * ent[tail] (RED.128);  ssum[h] += e
// ---------------------------------------------------------------------------
__global__ __launch_bounds__(256) void edge_soft_kernel(const float* __restrict__ ent,
                                                        const int* __restrict__ head,
                                                        const int* __restrict__ tail,
                                                        int E,
                                                        float* __restrict__ out) {
    int lane = threadIdx.x & 31;
    int gw   = (blockIdx.x * blockDim.x + threadIdx.x) >> 5;
    int tot  = (gridDim.x * blockDim.x) >> 5;
    for (int e = gw; e < E; e += tot) {
        int h = head[e], t = tail[e];
        float m  = __int_as_float(g_m[h]);
        float ex = __expf(g_w[e] - m);
        float4 tv = *(const float4*)&ent[(size_t)t * D + lane * 4];
        red_add_v4(&out[(size_t)h * D + lane * 4],
                   ex * tv.x, ex * tv.y, ex * tv.z, ex * tv.w);
        if (lane == 0) atomicAdd(&g_ssum[h], ex);
    }
}

// ---------------------------------------------------------------------------
// Kernel 6: out /= ssum (rows with no edges stay 0)
// ---------------------------------------------------------------------------
__global__ __launch_bounds__(256) void finalize_out_kernel(float* __restrict__ out, int n_ent) {
    int idx = blockIdx.x * blockDim.x + threadIdx.x;   // over n_ent * 32 (float4 each)
    if (idx >= n_ent * (D / 4)) return;
    int row = idx >> 5;
    float s = g_ssum[row];
    float inv = (s > 0.f) ? (1.f / s) : 0.f;
    float4 o = *(float4*)&out[(size_t)idx * 4];
    o.x *= inv; o.y *= inv; o.z *= inv; o.w *= inv;
    *(float4*)&out[(size_t)idx * 4] = o;
}

// ---------------------------------------------------------------------------
extern "C" void kernel_launch(void* const* d_in, const int* in_sizes, int n_in,
                              void* d_out, int out_size) {
    const float* ent    = (const float*)d_in[0];   // [n_ent, 128]
    const float* weight = (const float*)d_in[3];   // [32, 128]
    const float* qT     = (const float*)d_in[4];   // [128, 128]
    const float* kT     = (const float*)d_in[5];
    const float* vT     = (const float*)d_in[6];
    const int*   eidx   = (const int*)d_in[7];     // [2, E]
    const int*   etype  = (const int*)d_in[8];     // [E]

    int E     = in_sizes[8];
    int n_ent = in_sizes[0] / D;
    const int* head = eidx;
    const int* tail = eidx + E;
    float* out = (float*)d_out;

    void *pS, *pN, *pM, *pSs;
    cudaGetSymbolAddress(&pS,  g_S);
    cudaGetSymbolAddress(&pN,  g_normA);
    cudaGetSymbolAddress(&pM,  g_m);
    cudaGetSymbolAddress(&pSs, g_ssum);
    cudaMemsetAsync(pS,  0, (size_t)n_ent * D * sizeof(float));
    cudaMemsetAsync(pN,  0, (size_t)n_ent * H * sizeof(float));
    cudaMemsetAsync(pM,  0, (size_t)n_ent * sizeof(int));
    cudaMemsetAsync(pSs, 0, (size_t)n_ent * sizeof(float));
    cudaMemsetAsync(d_out, 0, (size_t)out_size * sizeof(float));

    // Kernel 1: Q_all
    int smem_q = (D * D + 8 * 4 * D) * (int)sizeof(float);   // 80 KB
    cudaFuncSetAttribute(gemm_q_kernel, cudaFuncAttributeMaxDynamicSharedMemorySize, smem_q);
    gemm_q_kernel<<<148, 256, smem_q>>>(ent, qT, n_ent);

    // Kernel 2: edge phase A (dominant) — 384 threads (3 warps/SMSP), 1 block/SM
    int smem_e = (2 * D * D + (PA_THREADS / 32) * 4 * D) * (int)sizeof(float);  // 152 KB
    cudaFuncSetAttribute(edge_phaseA_kernel, cudaFuncAttributeMaxDynamicSharedMemorySize, smem_e);
    edge_phaseA_kernel<<<148, PA_THREADS, smem_e>>>(ent, weight, kT, vT, head, tail, etype, E);

    // Kernel 3
    int n3 = n_ent * (D / 4);
    finalize_kg_kernel<<<(n3 + 255) / 256, 256>>>(n_ent);

    // Kernel 4 / 5
    edge_w_kernel<<<2048, 256>>>(weight, head, tail, etype, E);
    edge_soft_kernel<<<2048, 256>>>(ent, head, tail, E, out);

    // Kernel 6
    finalize_out_kernel<<<(n3 + 255) / 256, 256>>>(out, n_ent);
}

// round 5
// speedup vs baseline: 2.1990x; 1.0783x over previous
#include <cuda_runtime.h>
#include <cuda_bf16.h>

#define D   128
#define H   4
#define MAX_ENT 100000
#define MAX_E   400000

typedef unsigned long long u64;

// ---------------- packed f32x2 helpers (SASS FFMA2 — only reachable via PTX) ----
__device__ __forceinline__ u64 pack2(float x) {
    u64 r; asm("mov.b64 %0, {%1, %1};" : "=l"(r) : "r"(__float_as_uint(x)));
    return r;
}
__device__ __forceinline__ void ffma2(u64 &acc, u64 a, u64 b) {
    asm("fma.rn.f32x2 %0, %1, %2, %0;" : "+l"(acc) : "l"(a), "l"(b));
}
__device__ __forceinline__ float lo2(u64 v) { return __uint_as_float((unsigned)v); }
__device__ __forceinline__ float hi2(u64 v) { return __uint_as_float((unsigned)(v >> 32)); }

__device__ __forceinline__ void red_add_v4(float* p, float a, float b, float c, float d) {
    asm volatile("red.global.add.v4.f32 [%0], {%1, %2, %3, %4};"
                 :: "l"(p), "f"(a), "f"(b), "f"(c), "f"(d) : "memory");
}

// ---------------- scratch (__device__ globals; no allocation allowed) ----------------
__device__ float g_Q[(size_t)MAX_ENT * D];      // entity_emb @ qTrans
__device__ float g_S[(size_t)MAX_ENT * D];      // phase-A accumulator -> kg_emb (in place)
__device__ float g_normA[(size_t)MAX_ENT * H];  // per-(entity,head) sum of exp(att)
__device__ float g_w[(size_t)MAX_E];            // per-edge scalar attention logit (phase B)
__device__ int   g_m[(size_t)MAX_ENT];          // per-entity max(w) as float bits (w >= 0)
__device__ float g_ssum[(size_t)MAX_ENT];       // per-entity softmax denominator

// ---------------------------------------------------------------------------
// Kernel 1: Q_all = entity_emb @ qTrans   (qT in SMEM, 4 rows per warp-iter, f32x2)
// ---------------------------------------------------------------------------
__global__ __launch_bounds__(256) void gemm_q_kernel(const float* __restrict__ ent,
                                                     const float* __restrict__ qT,
                                                     int n_ent) {
    extern __shared__ float sm[];
    float* qT_s = sm;                 // D*D floats
    float* u_s  = sm + D * D;         // nwarps*4*D floats
    int tid = threadIdx.x, lane = tid & 31, wid = tid >> 5;
    int nw = blockDim.x >> 5;

    for (int i = tid * 4; i < D * D; i += blockDim.x * 4)
        *(float4*)&qT_s[i] = *(const float4*)&qT[i];
    __syncthreads();

    float* u = u_s + wid * 4 * D;
    int gw  = blockIdx.x * nw + wid;
    int tot = gridDim.x * nw;

    for (int g = gw; g * 4 < n_ent; g += tot) {
        int r0 = g * 4;
        int n  = min(4, n_ent - r0);
        #pragma unroll
        for (int e = 0; e < 4; e++) {
            float4 tv = make_float4(0.f, 0.f, 0.f, 0.f);
            if (e < n) tv = *(const float4*)&ent[(size_t)(r0 + e) * D + lane * 4];
            *(float4*)&u[e * D + lane * 4] = tv;
        }
        __syncwarp();

        u64 a01[4] = {0,0,0,0}, a23[4] = {0,0,0,0};
        #pragma unroll 4
        for (int i = 0; i < D; i++) {
            ulonglong2 qv = *(ulonglong2*)&qT_s[i * D + lane * 4];
            #pragma unroll
            for (int e = 0; e < 4; e++) {
                u64 up = pack2(u[e * D + i]);
                ffma2(a01[e], up, qv.x);
                ffma2(a23[e], up, qv.y);
            }
        }
        #pragma unroll
        for (int e = 0; e < 4; e++) {
            if (e < n)
                *(float4*)&g_Q[(size_t)(r0 + e) * D + lane * 4] =
                    make_float4(lo2(a01[e]), hi2(a01[e]), lo2(a23[e]), hi2(a23[e]));
        }
        __syncwarp();
    }
}

// ---------------------------------------------------------------------------
// Kernel 2 (dominant): per-edge  u = ent[tail]*rel;  k = u@kT; v = u@vT;
//   att[h4] = clip(Q[head]·k per head, -10, 10); ea = exp(att)
//   atomically accumulate  S[head] += ea*v (RED.128),  normA[head,h4] += ea
// kT,vT resident in SMEM (128 KB); 8 edges per warp iteration (FMA-bound tile);
// u broadcast via LDS.128 float4; FFMA2 inner loop
// ---------------------------------------------------------------------------
#define PA_THREADS 384
#define ET 8   // edges per warp iteration
__global__ __launch_bounds__(PA_THREADS) void edge_phaseA_kernel(const float* __restrict__ ent,
                                                          const float* __restrict__ weight,
                                                          const float* __restrict__ kT,
                                                          const float* __restrict__ vT,
                                                          const int* __restrict__ head,
                                                          const int* __restrict__ tail,
                                                          const int* __restrict__ etype,
                                                          int E) {
    extern __shared__ float sm[];
    float* kT_s = sm;                  // D*D
    float* vT_s = sm + D * D;          // D*D
    float* u_s  = sm + 2 * D * D;      // nwarps*ET*D
    int tid = threadIdx.x, lane = tid & 31, wid = tid >> 5;
    int nw = blockDim.x >> 5;

    for (int i = tid * 4; i < 2 * D * D; i += blockDim.x * 4) {
        if (i < D * D) *(float4*)&sm[i] = *(const float4*)&kT[i];
        else           *(float4*)&sm[i] = *(const float4*)&vT[i - D * D];
    }
    __syncthreads();

    float* u = u_s + wid * ET * D;
    int gw  = blockIdx.x * nw + wid;
    int tot = gridDim.x * nw;

    for (int g = gw; g * ET < E; g += tot) {
        int e0 = g * ET;
        int n  = min(ET, E - e0);
        int hidx[ET];

        #pragma unroll
        for (int e = 0; e < ET; e++) {
            float4 uv = make_float4(0.f, 0.f, 0.f, 0.f);
            if (e < n) {
                int t = tail[e0 + e];
                int r = etype[e0 + e] - 1;
                hidx[e] = head[e0 + e];
                float4 tv = *(const float4*)&ent[(size_t)t * D + lane * 4];
                float4 rv = *(const float4*)&weight[(size_t)r * D + lane * 4];
                uv = make_float4(tv.x * rv.x, tv.y * rv.y, tv.z * rv.z, tv.w * rv.w);
            }
            *(float4*)&u[e * D + lane * 4] = uv;
        }
        __syncwarp();

        // packed accumulators: columns (0,1) and (2,3) per edge
        u64 k01[ET], k23[ET], v01[ET], v23[ET];
        #pragma unroll
        for (int e = 0; e < ET; e++) { k01[e] = 0; k23[e] = 0; v01[e] = 0; v23[e] = 0; }

        #pragma unroll 2
        for (int i4 = 0; i4 < D / 4; i4++) {
            // one LDS.128 broadcast per edge covers 4 inner steps
            float4 uq[ET];
            #pragma unroll
            for (int e = 0; e < ET; e++) uq[e] = *(float4*)&u[e * D + i4 * 4];

            #pragma unroll
            for (int s = 0; s < 4; s++) {
                int i = i4 * 4 + s;
                ulonglong2 kv = *(ulonglong2*)&kT_s[i * D + lane * 4];
                ulonglong2 vv = *(ulonglong2*)&vT_s[i * D + lane * 4];
                #pragma unroll
                for (int e = 0; e < ET; e++) {
                    float us = (s == 0) ? uq[e].x : (s == 1) ? uq[e].y
                             : (s == 2) ? uq[e].z : uq[e].w;
                    u64 up = pack2(us);
                    ffma2(k01[e], up, kv.x);
                    ffma2(k23[e], up, kv.y);
                    ffma2(v01[e], up, vv.x);
                    ffma2(v23[e], up, vv.y);
                }
            }
        }

        #pragma unroll
        for (int e = 0; e < ET; e++) {
            if (e >= n) break;
            int h = hidx[e];
            float4 qv = *(const float4*)&g_Q[(size_t)h * D + lane * 4];
            float p = qv.x * lo2(k01[e]) + qv.y * hi2(k01[e])
                    + qv.z * lo2(k23[e]) + qv.w * hi2(k23[e]);
            // lanes 8*hh .. 8*hh+7 jointly own head slice hh = lane/8 (32 columns)
            p += __shfl_xor_sync(0xffffffffu, p, 1);
            p += __shfl_xor_sync(0xffffffffu, p, 2);
            p += __shfl_xor_sync(0xffffffffu, p, 4);
            float att = fminf(fmaxf(p, -10.f), 10.f);
            float ea  = __expf(att);
            red_add_v4(&g_S[(size_t)h * D + lane * 4],
                       ea * lo2(v01[e]), ea * hi2(v01[e]),
                       ea * lo2(v23[e]), ea * hi2(v23[e]));
            if ((lane & 7) == 0)
                atomicAdd(&g_normA[(size_t)h * H + (lane >> 3)], ea);
        }
        __syncwarp();
    }
}

// ---------------------------------------------------------------------------
// Kernel 3: kg_emb = S / (normA + 1e-8)  (in place in g_S)
// ---------------------------------------------------------------------------
__global__ __launch_bounds__(256) void finalize_kg_kernel(int n_ent) {
    int idx = blockIdx.x * blockDim.x + threadIdx.x;   // over n_ent * 32 (float4 each)
    if (idx >= n_ent * (D / 4)) return;
    int row = idx >> 5;
    int q   = idx & 31;                                 // float4 index within row
    float inv = 1.f / (g_normA[(size_t)row * H + (q >> 3)] + 1e-8f);
    float4 s = *(float4*)&g_S[(size_t)idx * 4];
    s.x *= inv; s.y *= inv; s.z *= inv; s.w *= inv;
    *(float4*)&g_S[(size_t)idx * 4] = s;
}

// ---------------------------------------------------------------------------
// Kernel 4: per-edge w = (||kg[h]*rel|| * ||kg[t]*rel||)^2 = sumsq_h * sumsq_t
//           segment max via int-atomicMax (w >= 0). One warp per edge.
// ---------------------------------------------------------------------------
__global__ __launch_bounds__(256) void edge_w_kernel(const float* __restrict__ weight,
                                                     const int* __restrict__ head,
                                                     const int* __restrict__ tail,
                                                     const int* __restrict__ etype,
                                                     int E) {
    int lane = threadIdx.x & 31;
    int gw   = (blockIdx.x * blockDim.x + threadIdx.x) >> 5;
    int tot  = (gridDim.x * blockDim.x) >> 5;
    for (int e = gw; e < E; e += tot) {
        int h = head[e], t = tail[e], r = etype[e] - 1;
        float4 rv = *(const float4*)&weight[(size_t)r * D + lane * 4];
        float4 hv = *(const float4*)&g_S[(size_t)h * D + lane * 4];
        float4 tv = *(const float4*)&g_S[(size_t)t * D + lane * 4];
        float ph = 0.f, pt = 0.f;
        float x;
        x = hv.x * rv.x; ph = fmaf(x, x, ph);
        x = hv.y * rv.y; ph = fmaf(x, x, ph);
        x = hv.z * rv.z; ph = fmaf(x, x, ph);
        x = hv.w * rv.w; ph = fmaf(x, x, ph);
        x = tv.x * rv.x; pt = fmaf(x, x, pt);
        x = tv.y * rv.y; pt = fmaf(x, x, pt);
        x = tv.z * rv.z; pt = fmaf(x, x, pt);
        x = tv.w * rv.w; pt = fmaf(x, x, pt);
        #pragma unroll
        for (int off = 16; off > 0; off >>= 1) {
            ph += __shfl_xor_sync(0xffffffffu, ph, off);
            pt += __shfl_xor_sync(0xffffffffu, pt, off);
        }
        float w = ph * pt;   // >= 0
        if (lane == 0) {
            g_w[e] = w;
            atomicMax(&g_m[h], __float_as_int(w));
        }
    }
}

// ---------------------------------------------------------------------------
// Kernel 5: e = exp(w - m[h]);  out[h] += e * ent[tail] (RED.128);  ssum[h] += e
// ---------------------------------------------------------------------------
__global__ __launch_bounds__(256) void edge_soft_kernel(const float* __restrict__ ent,
                                                        const int* __restrict__ head,
                                                        const int* __restrict__ tail,
                                                        int E,
                                                        float* __restrict__ out) {
    int lane = threadIdx.x & 31;
    int gw   = (blockIdx.x * blockDim.x + threadIdx.x) >> 5;
    int tot  = (gridDim.x * blockDim.x) >> 5;
    for (int e = gw; e < E; e += tot) {
        int h = head[e], t = tail[e];
        float m  = __int_as_float(g_m[h]);
        float ex = __expf(g_w[e] - m);
        float4 tv = *(const float4*)&ent[(size_t)t * D + lane * 4];
        red_add_v4(&out[(size_t)h * D + lane * 4],
                   ex * tv.x, ex * tv.y, ex * tv.z, ex * tv.w);
        if (lane == 0) atomicAdd(&g_ssum[h], ex);
    }
}

// ---------------------------------------------------------------------------
// Kernel 6: out /= ssum (rows with no edges stay 0)
// ---------------------------------------------------------------------------
__global__ __launch_bounds__(256) void finalize_out_kernel(float* __restrict__ out, int n_ent) {
    int idx = blockIdx.x * blockDim.x + threadIdx.x;   // over n_ent * 32 (float4 each)
    if (idx >= n_ent * (D / 4)) return;
    int row = idx >> 5;
    float s = g_ssum[row];
    float inv = (s > 0.f) ? (1.f / s) : 0.f;
    float4 o = *(float4*)&out[(size_t)idx * 4];
    o.x *= inv; o.y *= inv; o.z *= inv; o.w *= inv;
    *(float4*)&out[(size_t)idx * 4] = o;
}

// ---------------------------------------------------------------------------
extern "C" void kernel_launch(void* const* d_in, const int* in_sizes, int n_in,
                              void* d_out, int out_size) {
    const float* ent    = (const float*)d_in[0];   // [n_ent, 128]
    const float* weight = (const float*)d_in[3];   // [32, 128]
    const float* qT     = (const float*)d_in[4];   // [128, 128]
    const float* kT     = (const float*)d_in[5];
    const float* vT     = (const float*)d_in[6];
    const int*   eidx   = (const int*)d_in[7];     // [2, E]
    const int*   etype  = (const int*)d_in[8];     // [E]

    int E     = in_sizes[8];
    int n_ent = in_sizes[0] / D;
    const int* head = eidx;
    const int* tail = eidx + E;
    float* out = (float*)d_out;

    void *pS, *pN, *pM, *pSs;
    cudaGetSymbolAddress(&pS,  g_S);
    cudaGetSymbolAddress(&pN,  g_normA);
    cudaGetSymbolAddress(&pM,  g_m);
    cudaGetSymbolAddress(&pSs, g_ssum);
    cudaMemsetAsync(pS,  0, (size_t)n_ent * D * sizeof(float));
    cudaMemsetAsync(pN,  0, (size_t)n_ent * H * sizeof(float));
    cudaMemsetAsync(pM,  0, (size_t)n_ent * sizeof(int));
    cudaMemsetAsync(pSs, 0, (size_t)n_ent * sizeof(float));
    cudaMemsetAsync(d_out, 0, (size_t)out_size * sizeof(float));

    // Kernel 1: Q_all
    int smem_q = (D * D + 8 * 4 * D) * (int)sizeof(float);   // 80 KB
    cudaFuncSetAttribute(gemm_q_kernel, cudaFuncAttributeMaxDynamicSharedMemorySize, smem_q);
    gemm_q_kernel<<<148, 256, smem_q>>>(ent, qT, n_ent);

    // Kernel 2: edge phase A (dominant) — 384 threads, 8 edges/warp-iter, 1 block/SM
    int smem_e = (2 * D * D + (PA_THREADS / 32) * ET * D) * (int)sizeof(float);  // 176 KB
    cudaFuncSetAttribute(edge_phaseA_kernel, cudaFuncAttributeMaxDynamicSharedMemorySize, smem_e);
    edge_phaseA_kernel<<<148, PA_THREADS, smem_e>>>(ent, weight, kT, vT, head, tail, etype, E);

    // Kernel 3
    int n3 = n_ent * (D / 4);
    finalize_kg_kernel<<<(n3 + 255) / 256, 256>>>(n_ent);

    // Kernel 4 / 5
    edge_w_kernel<<<2048, 256>>>(weight, head, tail, etype, E);
    edge_soft_kernel<<<2048, 256>>>(ent, head, tail, E, out);

    // Kernel 6
    finalize_out_kernel<<<(n3 + 255) / 256, 256>>>(out, n_ent);
}

// round 6
// speedup vs baseline: 2.2058x; 1.0031x over previous
#include <cuda_runtime.h>
#include <cuda_bf16.h>

#define D   128
#define H   4
#define R_MAX 32
#define MAX_ENT 100000
#define MAX_E   400000

typedef unsigned long long u64;

// ---------------- packed f32x2 helpers (SASS FFMA2/FADD2 — PTX-only) ----------
__device__ __forceinline__ u64 pack2(float x) {
    u64 r; asm("mov.b64 %0, {%1, %1};" : "=l"(r) : "r"(__float_as_uint(x)));
    return r;
}
__device__ __forceinline__ void ffma2(u64 &acc, u64 a, u64 b) {
    asm("fma.rn.f32x2 %0, %1, %2, %0;" : "+l"(acc) : "l"(a), "l"(b));
}
__device__ __forceinline__ u64 add2(u64 a, u64 b) {
    u64 r; asm("add.rn.f32x2 %0, %1, %2;" : "=l"(r) : "l"(a), "l"(b));
    return r;
}
__device__ __forceinline__ float lo2(u64 v) { return __uint_as_float((unsigned)v); }
__device__ __forceinline__ float hi2(u64 v) { return __uint_as_float((unsigned)(v >> 32)); }

__device__ __forceinline__ void red_add_v4(float* p, float a, float b, float c, float d) {
    asm volatile("red.global.add.v4.f32 [%0], {%1, %2, %3, %4};"
                 :: "l"(p), "f"(a), "f"(b), "f"(c), "f"(d) : "memory");
}

// ---------------- scratch (__device__ globals; no allocation allowed) ----------------
__device__ float g_C[(size_t)MAX_ENT * H * D];  // per-entity att-projection: layout [ent][lane*16 + j*4 + h]
__device__ float g_S[(size_t)MAX_ENT * D];      // phase-A accumulator -> kg_emb (in place)
__device__ float g_normA[(size_t)MAX_ENT * H];  // per-(entity,head) sum of exp(att)
__device__ float g_N[(size_t)MAX_ENT * R_MAX];  // sumsq(kg*rel) per (entity, relation)
__device__ float g_w[(size_t)MAX_E];            // per-edge scalar attention logit (phase B)
__device__ int   g_m[(size_t)MAX_ENT];          // per-entity max(w) as float bits (w >= 0)
__device__ float g_ssum[(size_t)MAX_ENT];       // per-entity softmax denominator

// ---------------------------------------------------------------------------
// Kernel 1: per entity -> q = ent@qT, then C[ent][h][i] = sum_{c in slice_h} kT[i][c]*q[c]
// qT (64KB) + kT transposed (64KB) in SMEM; 4 entities per warp iteration.
// C layout: g_C[ent*512 + lane*16 + j*4 + h] = c_h[i = lane*4 + j]
// ---------------------------------------------------------------------------
__global__ __launch_bounds__(256) void prep_qc_kernel(const float* __restrict__ ent,
                                                      const float* __restrict__ qT,
                                                      const float* __restrict__ kT,
                                                      int n_ent) {
    extern __shared__ float sm[];
    float* qT_s  = sm;                  // D*D
    float* kTt_s = sm + D * D;          // D*D, kTt[c*D + i] = kT[i*D + c]
    float* u_s   = sm + 2 * D * D;      // 8 warps * 4 * D
    float* q_s   = sm + 2 * D * D + 8 * 4 * D;   // 8 warps * 4 * D
    int tid = threadIdx.x, lane = tid & 31, wid = tid >> 5;
    int nw = blockDim.x >> 5;

    for (int i = tid * 4; i < D * D; i += blockDim.x * 4)
        *(float4*)&qT_s[i] = *(const float4*)&qT[i];
    for (int idx = tid; idx < D * D; idx += blockDim.x) {
        int c = idx >> 7, i = idx & 127;
        kTt_s[idx] = kT[i * D + c];     // conflict-free STS; one-time transposed load
    }
    __syncthreads();

    float* u = u_s + wid * 4 * D;
    float* q = q_s + wid * 4 * D;
    int gw  = blockIdx.x * nw + wid;
    int tot = gridDim.x * nw;

    for (int g = gw; g * 4 < n_ent; g += tot) {
        int r0 = g * 4;
        int n  = min(4, n_ent - r0);
        #pragma unroll
        for (int e = 0; e < 4; e++) {
            float4 tv = make_float4(0.f, 0.f, 0.f, 0.f);
            if (e < n) tv = *(const float4*)&ent[(size_t)(r0 + e) * D + lane * 4];
            *(float4*)&u[e * D + lane * 4] = tv;
        }
        __syncwarp();

        // q = ent @ qT
        u64 a01[4] = {0,0,0,0}, a23[4] = {0,0,0,0};
        #pragma unroll 4
        for (int i = 0; i < D; i++) {
            ulonglong2 qv = *(ulonglong2*)&qT_s[i * D + lane * 4];
            #pragma unroll
            for (int e = 0; e < 4; e++) {
                u64 up = pack2(u[e * D + i]);
                ffma2(a01[e], up, qv.x);
                ffma2(a23[e], up, qv.y);
            }
        }
        #pragma unroll
        for (int e = 0; e < 4; e++)
            *(float4*)&q[e * D + lane * 4] =
                make_float4(lo2(a01[e]), hi2(a01[e]), lo2(a23[e]), hi2(a23[e]));
        __syncwarp();

        // C: c_h[i] = sum_{c in [32h,32h+32)} q[c] * kTt[c][i]
        // cj01[e][h] packs i = (lane*4+0, lane*4+1); cj23 packs (+2, +3)
        u64 cj01[4][H], cj23[4][H];
        #pragma unroll
        for (int e = 0; e < 4; e++)
            #pragma unroll
            for (int h = 0; h < H; h++) { cj01[e][h] = 0; cj23[e][h] = 0; }

        #pragma unroll
        for (int h = 0; h < H; h++) {
            #pragma unroll 8
            for (int cc = 0; cc < 32; cc++) {
                int c = h * 32 + cc;
                ulonglong2 kv = *(ulonglong2*)&kTt_s[c * D + lane * 4];
                #pragma unroll
                for (int e = 0; e < 4; e++) {
                    u64 qb = pack2(q[e * D + c]);
                    ffma2(cj01[e][h], qb, kv.x);
                    ffma2(cj23[e][h], qb, kv.y);
                }
            }
        }

        #pragma unroll
        for (int e = 0; e < 4; e++) {
            if (e >= n) break;
            float* Cb = &g_C[(size_t)(r0 + e) * (H * D) + lane * 16];
            *(float4*)&Cb[0]  = make_float4(lo2(cj01[e][0]), lo2(cj01[e][1]), lo2(cj01[e][2]), lo2(cj01[e][3]));
            *(float4*)&Cb[4]  = make_float4(hi2(cj01[e][0]), hi2(cj01[e][1]), hi2(cj01[e][2]), hi2(cj01[e][3]));
            *(float4*)&Cb[8]  = make_float4(lo2(cj23[e][0]), lo2(cj23[e][1]), lo2(cj23[e][2]), lo2(cj23[e][3]));
            *(float4*)&Cb[12] = make_float4(hi2(cj23[e][0]), hi2(cj23[e][1]), hi2(cj23[e][2]), hi2(cj23[e][3]));
        }
        __syncwarp();
    }
}

// ---------------------------------------------------------------------------
// Kernel 2 (dominant): per-edge  u = ent[tail]*rel;
//   att_h = clip(u . C[head][h], -10, 10) at staging (C-gather + f32x2 butterfly);
//   v = u @ vT  (only remaining matvec — FMA floor halved);
//   S[head] += ea*v (RED.128), normA[head,h] += ea
// vT resident in SMEM (64 KB); 8 edges per warp iteration; 512 threads
// ---------------------------------------------------------------------------
#define PA_THREADS 512
#define ET 8
__global__ __launch_bounds__(PA_THREADS) void edge_phaseA_kernel(const float* __restrict__ ent,
                                                          const float* __restrict__ weight,
                                                          const float* __restrict__ vT,
                                                          const int* __restrict__ head,
                                                          const int* __restrict__ tail,
                                                          const int* __restrict__ etype,
                                                          int E) {
    extern __shared__ float sm[];
    float* vT_s = sm;                  // D*D
    float* u_s  = sm + D * D;          // nwarps*ET*D
    int tid = threadIdx.x, lane = tid & 31, wid = tid >> 5;
    int nw = blockDim.x >> 5;

    for (int i = tid * 4; i < D * D; i += blockDim.x * 4)
        *(float4*)&sm[i] = *(const float4*)&vT[i];
    __syncthreads();

    float* u = u_s + wid * ET * D;
    int gw  = blockIdx.x * nw + wid;
    int tot = gridDim.x * nw;
    int hh  = lane >> 3;   // head slice owned by this lane's output columns

    for (int g = gw; g * ET < E; g += tot) {
        int e0 = g * ET;
        int n  = min(ET, E - e0);
        int hidx[ET];
        float eaArr[ET];

        #pragma unroll
        for (int e = 0; e < ET; e++) {
            if (e < n) {
                int t = tail[e0 + e];
                int r = etype[e0 + e] - 1;
                int h = head[e0 + e];
                hidx[e] = h;
                float4 tv = *(const float4*)&ent[(size_t)t * D + lane * 4];
                float4 rv = *(const float4*)&weight[(size_t)r * D + lane * 4];
                float4 uv = make_float4(tv.x * rv.x, tv.y * rv.y, tv.z * rv.z, tv.w * rv.w);
                *(float4*)&u[e * D + lane * 4] = uv;

                // att partials: p01 = (att_h0, att_h1), p23 = (att_h2, att_h3)
                const float* Cb = &g_C[(size_t)h * (H * D) + lane * 16];
                ulonglong2 L0 = *(const ulonglong2*)&Cb[0];
                ulonglong2 L1 = *(const ulonglong2*)&Cb[4];
                ulonglong2 L2 = *(const ulonglong2*)&Cb[8];
                ulonglong2 L3 = *(const ulonglong2*)&Cb[12];
                u64 p01 = 0, p23 = 0;
                ffma2(p01, pack2(uv.x), L0.x); ffma2(p23, pack2(uv.x), L0.y);
                ffma2(p01, pack2(uv.y), L1.x); ffma2(p23, pack2(uv.y), L1.y);
                ffma2(p01, pack2(uv.z), L2.x); ffma2(p23, pack2(uv.z), L2.y);
                ffma2(p01, pack2(uv.w), L3.x); ffma2(p23, pack2(uv.w), L3.y);
                #pragma unroll
                for (int off = 16; off > 0; off >>= 1) {
                    p01 = add2(p01, __shfl_xor_sync(0xffffffffu, p01, off));
                    p23 = add2(p23, __shfl_xor_sync(0xffffffffu, p23, off));
                }
                float att = (hh == 0) ? lo2(p01) : (hh == 1) ? hi2(p01)
                          : (hh == 2) ? lo2(p23) : hi2(p23);
                att = fminf(fmaxf(att, -10.f), 10.f);
                eaArr[e] = __expf(att);
            } else {
                *(float4*)&u[e * D + lane * 4] = make_float4(0.f, 0.f, 0.f, 0.f);
            }
        }
        __syncwarp();

        // v = u @ vT  (packed accumulators: columns (0,1) and (2,3) per edge)
        u64 v01[ET], v23[ET];
        #pragma unroll
        for (int e = 0; e < ET; e++) { v01[e] = 0; v23[e] = 0; }

        #pragma unroll 2
        for (int i4 = 0; i4 < D / 4; i4++) {
            float4 uq[ET];
            #pragma unroll
            for (int e = 0; e < ET; e++) uq[e] = *(float4*)&u[e * D + i4 * 4];

            #pragma unroll
            for (int s = 0; s < 4; s++) {
                int i = i4 * 4 + s;
                ulonglong2 vv = *(ulonglong2*)&vT_s[i * D + lane * 4];
                #pragma unroll
                for (int e = 0; e < ET; e++) {
                    float us = (s == 0) ? uq[e].x : (s == 1) ? uq[e].y
                             : (s == 2) ? uq[e].z : uq[e].w;
                    u64 up = pack2(us);
                    ffma2(v01[e], up, vv.x);
                    ffma2(v23[e], up, vv.y);
                }
            }
        }

        #pragma unroll
        for (int e = 0; e < ET; e++) {
            if (e >= n) break;
            int h = hidx[e];
            float ea = eaArr[e];
            red_add_v4(&g_S[(size_t)h * D + lane * 4],
                       ea * lo2(v01[e]), ea * hi2(v01[e]),
                       ea * lo2(v23[e]), ea * hi2(v23[e]));
            if ((lane & 7) == 0)
                atomicAdd(&g_normA[(size_t)h * H + hh], ea);
        }
        __syncwarp();
    }
}

// ---------------------------------------------------------------------------
// Kernel 3: kg_emb = S / (normA + 1e-8)  (in place in g_S)
// ---------------------------------------------------------------------------
__global__ __launch_bounds__(256) void finalize_kg_kernel(int n_ent) {
    int idx = blockIdx.x * blockDim.x + threadIdx.x;   // over n_ent * 32 (float4 each)
    if (idx >= n_ent * (D / 4)) return;
    int row = idx >> 5;
    int q   = idx & 31;
    float inv = 1.f / (g_normA[(size_t)row * H + (q >> 3)] + 1e-8f);
    float4 s = *(float4*)&g_S[(size_t)idx * 4];
    s.x *= inv; s.y *= inv; s.z *= inv; s.w *= inv;
    *(float4*)&g_S[(size_t)idx * 4] = s;
}

// ---------------------------------------------------------------------------
// Kernel 3b: N[ent][r] = sum_i kg[ent,i]^2 * weight[r,i]^2  (12.8 MB table, L2-resident)
// One warp per entity; lane owns one relation r.
// ---------------------------------------------------------------------------
__global__ __launch_bounds__(256) void ntable_kernel(const float* __restrict__ weight,
                                                     int n_ent, int R) {
    extern __shared__ float sm[];
    float* w2t   = sm;                 // [D][R_MAX]: w2t[i*R_MAX + r] = weight[r][i]^2
    float* kg2_s = sm + D * R_MAX;     // 8 warps * D
    int tid = threadIdx.x, lane = tid & 31, wid = tid >> 5;

    for (int idx = tid; idx < D * R_MAX; idx += blockDim.x) {
        int i = idx >> 5, r = idx & 31;
        float v = (r < R) ? weight[r * D + i] : 0.f;
        w2t[idx] = v * v;
    }
    __syncthreads();

    float* kg2 = kg2_s + wid * D;
    int gw  = blockIdx.x * (blockDim.x >> 5) + wid;
    int tot = gridDim.x * (blockDim.x >> 5);

    for (int e = gw; e < n_ent; e += tot) {
        float4 k = *(const float4*)&g_S[(size_t)e * D + lane * 4];
        *(float4*)&kg2[lane * 4] = make_float4(k.x * k.x, k.y * k.y, k.z * k.z, k.w * k.w);
        __syncwarp();
        float acc = 0.f;
        #pragma unroll 8
        for (int i4 = 0; i4 < D / 4; i4++) {
            float4 k2 = *(float4*)&kg2[i4 * 4];
            acc = fmaf(k2.x, w2t[(i4 * 4 + 0) * R_MAX + lane], acc);
            acc = fmaf(k2.y, w2t[(i4 * 4 + 1) * R_MAX + lane], acc);
            acc = fmaf(k2.z, w2t[(i4 * 4 + 2) * R_MAX + lane], acc);
            acc = fmaf(k2.w, w2t[(i4 * 4 + 3) * R_MAX + lane], acc);
        }
        g_N[(size_t)e * R_MAX + lane] = acc;
        __syncwarp();
    }
}

// ---------------------------------------------------------------------------
// Kernel 4: per-edge w = N[h][r] * N[t][r]; segment max via int-atomicMax (w >= 0).
// One THREAD per edge — two 4B L2 hits instead of two 512B row gathers.
// ---------------------------------------------------------------------------
__global__ __launch_bounds__(256) void edge_w_kernel(const int* __restrict__ head,
                                                     const int* __restrict__ tail,
                                                     const int* __restrict__ etype,
                                                     int E) {
    int idx = blockIdx.x * blockDim.x + threadIdx.x;
    int tot = gridDim.x * blockDim.x;
    for (int e = idx; e < E; e += tot) {
        int h = head[e], t = tail[e], r = etype[e] - 1;
        float w = g_N[(size_t)h * R_MAX + r] * g_N[(size_t)t * R_MAX + r];
        g_w[e] = w;
        atomicMax(&g_m[h], __float_as_int(w));
    }
}

// ---------------------------------------------------------------------------
// Kernel 5: e = exp(w - m[h]);  out[h] += e * ent[tail] (RED.128);  ssum[h] += e
// ---------------------------------------------------------------------------
__global__ __launch_bounds__(256) void edge_soft_kernel(const float* __restrict__ ent,
                                                        const int* __restrict__ head,
                                                        const int* __restrict__ tail,
                                                        int E,
                                                        float* __restrict__ out) {
    int lane = threadIdx.x & 31;
    int gw   = (blockIdx.x * blockDim.x + threadIdx.x) >> 5;
    int tot  = (gridDim.x * blockDim.x) >> 5;
    for (int e = gw; e < E; e += tot) {
        int h = head[e], t = tail[e];
        float m  = __int_as_float(g_m[h]);
        float ex = __expf(g_w[e] - m);
        float4 tv = *(const float4*)&ent[(size_t)t * D + lane * 4];
        red_add_v4(&out[(size_t)h * D + lane * 4],
                   ex * tv.x, ex * tv.y, ex * tv.z, ex * tv.w);
        if (lane == 0) atomicAdd(&g_ssum[h], ex);
    }
}

// ---------------------------------------------------------------------------
// Kernel 6: out /= ssum (rows with no edges stay 0)
// ---------------------------------------------------------------------------
__global__ __launch_bounds__(256) void finalize_out_kernel(float* __restrict__ out, int n_ent) {
    int idx = blockIdx.x * blockDim.x + threadIdx.x;
    if (idx >= n_ent * (D / 4)) return;
    int row = idx >> 5;
    float s = g_ssum[row];
    float inv = (s > 0.f) ? (1.f / s) : 0.f;
    float4 o = *(float4*)&out[(size_t)idx * 4];
    o.x *= inv; o.y *= inv; o.z *= inv; o.w *= inv;
    *(float4*)&out[(size_t)idx * 4] = o;
}

// ---------------------------------------------------------------------------
extern "C" void kernel_launch(void* const* d_in, const int* in_sizes, int n_in,
                              void* d_out, int out_size) {
    const float* ent    = (const float*)d_in[0];   // [n_ent, 128]
    const float* weight = (const float*)d_in[3];   // [R, 128]
    const float* qT     = (const float*)d_in[4];   // [128, 128]
    const float* kT     = (const float*)d_in[5];
    const float* vT     = (const float*)d_in[6];
    const int*   eidx   = (const int*)d_in[7];     // [2, E]
    const int*   etype  = (const int*)d_in[8];     // [E]

    int E     = in_sizes[8];
    int n_ent = in_sizes[0] / D;
    int R     = in_sizes[3] / D;
    const int* head = eidx;
    const int* tail = eidx + E;
    float* out = (float*)d_out;

    void *pS, *pN, *pM, *pSs;
    cudaGetSymbolAddress(&pS,  g_S);
    cudaGetSymbolAddress(&pN,  g_normA);
    cudaGetSymbolAddress(&pM,  g_m);
    cudaGetSymbolAddress(&pSs, g_ssum);
    cudaMemsetAsync(pS,  0, (size_t)n_ent * D * sizeof(float));
    cudaMemsetAsync(pN,  0, (size_t)n_ent * H * sizeof(float));
    cudaMemsetAsync(pM,  0, (size_t)n_ent * sizeof(int));
    cudaMemsetAsync(pSs, 0, (size_t)n_ent * sizeof(float));
    cudaMemsetAsync(d_out, 0, (size_t)out_size * sizeof(float));

    // Kernel 1: q + C precompute (160 KB SMEM)
    int smem_qc = (2 * D * D + 2 * 8 * 4 * D) * (int)sizeof(float);
    cudaFuncSetAttribute(prep_qc_kernel, cudaFuncAttributeMaxDynamicSharedMemorySize, smem_qc);
    prep_qc_kernel<<<148, 256, smem_qc>>>(ent, qT, kT, n_ent);

    // Kernel 2: edge phase A — 512 threads, 8 edges/warp-iter, 128 KB SMEM
    int smem_e = (D * D + (PA_THREADS / 32) * ET * D) * (int)sizeof(float);
    cudaFuncSetAttribute(edge_phaseA_kernel, cudaFuncAttributeMaxDynamicSharedMemorySize, smem_e);
    edge_phaseA_kernel<<<148, PA_THREADS, smem_e>>>(ent, weight, vT, head, tail, etype, E);

    // Kernel 3: normalize kg
    int n3 = n_ent * (D / 4);
    finalize_kg_kernel<<<(n3 + 255) / 256, 256>>>(n_ent);

    // Kernel 3b: N table
    int smem_n = (D * R_MAX + 8 * D) * (int)sizeof(float);
    ntable_kernel<<<512, 256, smem_n>>>(weight, n_ent, R);

    // Kernel 4 / 5
    edge_w_kernel<<<1024, 256>>>(head, tail, etype, E);
    edge_soft_kernel<<<2048, 256>>>(ent, head, tail, E, out);

    // Kernel 6
    finalize_out_kernel<<<(n3 + 255) / 256, 256>>>(out, n_ent);
}

// round 8
// speedup vs baseline: 2.3734x; 1.0760x over previous
#include <cuda_runtime.h>
#include <cuda_bf16.h>

#define D   128
#define H   4
#define R_MAX 32
#define MAX_ENT 100000
#define MAX_E   400000

typedef unsigned long long u64;

// ---------------- packed f32x2 helpers (SASS FFMA2/FADD2 — PTX-only) ----------
__device__ __forceinline__ u64 pack2(float x) {
    u64 r; asm("mov.b64 %0, {%1, %1};" : "=l"(r) : "r"(__float_as_uint(x)));
    return r;
}
__device__ __forceinline__ void ffma2(u64 &acc, u64 a, u64 b) {
    asm("fma.rn.f32x2 %0, %1, %2, %0;" : "+l"(acc) : "l"(a), "l"(b));
}
__device__ __forceinline__ u64 add2(u64 a, u64 b) {
    u64 r; asm("add.rn.f32x2 %0, %1, %2;" : "=l"(r) : "l"(a), "l"(b));
    return r;
}
__device__ __forceinline__ float lo2(u64 v) { return __uint_as_float((unsigned)v); }
__device__ __forceinline__ float hi2(u64 v) { return __uint_as_float((unsigned)(v >> 32)); }

__device__ __forceinline__ void red_add_v4(float* p, float a, float b, float c, float d) {
    asm volatile("red.global.add.v4.f32 [%0], {%1, %2, %3, %4};"
                 :: "l"(p), "f"(a), "f"(b), "f"(c), "f"(d) : "memory");
}

// ---------------- scratch (__device__ globals; no allocation allowed) ----------------
__device__ float g_C[(size_t)MAX_ENT * H * D];  // per-entity att-projection: [ent][lane*16 + j*4 + h]
__device__ float g_S[(size_t)MAX_ENT * D];      // phase-A accumulator (un-normalized kg)
__device__ float g_normA[(size_t)MAX_ENT * H];  // per-(entity,head) sum of exp(att)
__device__ float g_N[(size_t)MAX_ENT * R_MAX];  // sumsq(kg*rel) per (entity, relation)
__device__ float g_w[(size_t)MAX_E];            // per-edge scalar attention logit (phase B)
__device__ int   g_m[(size_t)MAX_ENT];          // per-entity max(w) as float bits (w >= 0)
__device__ float g_ssum[(size_t)MAX_ENT];       // per-entity softmax denominator

// trivial launch used only to align the profiler's capture window onto phase A
__global__ void noop_kernel() {}

// ---------------------------------------------------------------------------
// Kernel 1: per entity -> q = ent@qT, then C[ent][h][i] = sum_{c in slice_h} kT[i][c]*q[c]
// qT (64KB) + kT transposed (64KB) in SMEM; 4 entities per warp iteration; 384 thr.
// C layout: g_C[ent*512 + lane*16 + j*4 + h] = c_h[i = lane*4 + j]
// ---------------------------------------------------------------------------
#define PQ_THREADS 384
#define PQ_WARPS   (PQ_THREADS / 32)
__global__ __launch_bounds__(PQ_THREADS) void prep_qc_kernel(const float* __restrict__ ent,
                                                      const float* __restrict__ qT,
                                                      const float* __restrict__ kT,
                                                      int n_ent) {
    extern __shared__ float sm[];
    float* qT_s  = sm;                  // D*D
    float* kTt_s = sm + D * D;          // D*D, kTt[c*D + i] = kT[i*D + c]
    float* u_s   = sm + 2 * D * D;                       // PQ_WARPS * 4 * D
    float* q_s   = sm + 2 * D * D + PQ_WARPS * 4 * D;    // PQ_WARPS * 4 * D
    int tid = threadIdx.x, lane = tid & 31, wid = tid >> 5;
    int nw = blockDim.x >> 5;

    for (int i = tid * 4; i < D * D; i += blockDim.x * 4)
        *(float4*)&qT_s[i] = *(const float4*)&qT[i];
    for (int idx = tid; idx < D * D; idx += blockDim.x) {
        int c = idx >> 7, i = idx & 127;
        kTt_s[idx] = kT[i * D + c];
    }
    __syncthreads();

    float* u = u_s + wid * 4 * D;
    float* q = q_s + wid * 4 * D;
    int gw  = blockIdx.x * nw + wid;
    int tot = gridDim.x * nw;

    for (int g = gw; g * 4 < n_ent; g += tot) {
        int r0 = g * 4;
        int n  = min(4, n_ent - r0);
        #pragma unroll
        for (int e = 0; e < 4; e++) {
            float4 tv = make_float4(0.f, 0.f, 0.f, 0.f);
            if (e < n) tv = *(const float4*)&ent[(size_t)(r0 + e) * D + lane * 4];
            *(float4*)&u[e * D + lane * 4] = tv;
        }
        __syncwarp();

        // q = ent @ qT
        u64 a01[4] = {0,0,0,0}, a23[4] = {0,0,0,0};
        #pragma unroll 4
        for (int i = 0; i < D; i++) {
            ulonglong2 qv = *(ulonglong2*)&qT_s[i * D + lane * 4];
            #pragma unroll
            for (int e = 0; e < 4; e++) {
                u64 up = pack2(u[e * D + i]);
                ffma2(a01[e], up, qv.x);
                ffma2(a23[e], up, qv.y);
            }
        }
        #pragma unroll
        for (int e = 0; e < 4; e++)
            *(float4*)&q[e * D + lane * 4] =
                make_float4(lo2(a01[e]), hi2(a01[e]), lo2(a23[e]), hi2(a23[e]));
        __syncwarp();

        // C: c_h[i] = sum_{c in [32h,32h+32)} q[c] * kTt[c][i]
        u64 cj01[4][H], cj23[4][H];
        #pragma unroll
        for (int e = 0; e < 4; e++)
            #pragma unroll
            for (int h = 0; h < H; h++) { cj01[e][h] = 0; cj23[e][h] = 0; }

        #pragma unroll
        for (int h = 0; h < H; h++) {
            #pragma unroll 8
            for (int cc = 0; cc < 32; cc++) {
                int c = h * 32 + cc;
                ulonglong2 kv = *(ulonglong2*)&kTt_s[c * D + lane * 4];
                #pragma unroll
                for (int e = 0; e < 4; e++) {
                    u64 qb = pack2(q[e * D + c]);
                    ffma2(cj01[e][h], qb, kv.x);
                    ffma2(cj23[e][h], qb, kv.y);
                }
            }
        }

        #pragma unroll
        for (int e = 0; e < 4; e++) {
            if (e >= n) break;
            float* Cb = &g_C[(size_t)(r0 + e) * (H * D) + lane * 16];
            *(float4*)&Cb[0]  = make_float4(lo2(cj01[e][0]), lo2(cj01[e][1]), lo2(cj01[e][2]), lo2(cj01[e][3]));
            *(float4*)&Cb[4]  = make_float4(hi2(cj01[e][0]), hi2(cj01[e][1]), hi2(cj01[e][2]), hi2(cj01[e][3]));
            *(float4*)&Cb[8]  = make_float4(lo2(cj23[e][0]), lo2(cj23[e][1]), lo2(cj23[e][2]), lo2(cj23[e][3]));
            *(float4*)&Cb[12] = make_float4(hi2(cj23[e][0]), hi2(cj23[e][1]), hi2(cj23[e][2]), hi2(cj23[e][3]));
        }
        __syncwarp();
    }
}

// ---------------------------------------------------------------------------
// Kernel 2 (dominant): per-edge  u = ent[tail]*rel;
//   att_h = clip(u . C[head][h], -10, 10) at staging (C-gather + f32x2 butterfly);
//   v = u @ vT;  S[head] += ea*v (RED.128), normA[head,h] += ea
// vT resident in SMEM (64 KB); 8 edges per warp iteration; 512 threads
// ---------------------------------------------------------------------------
#define PA_THREADS 512
#define ET 8
__global__ __launch_bounds__(PA_THREADS) void edge_phaseA_kernel(const float* __restrict__ ent,
                                                          const float* __restrict__ weight,
                                                          const float* __restrict__ vT,
                                                          const int* __restrict__ head,
                                                          const int* __restrict__ tail,
                                                          const int* __restrict__ etype,
                                                          int E) {
    extern __shared__ float sm[];
    float* vT_s = sm;                  // D*D
    float* u_s  = sm + D * D;          // nwarps*ET*D
    int tid = threadIdx.x, lane = tid & 31, wid = tid >> 5;
    int nw = blockDim.x >> 5;

    for (int i = tid * 4; i < D * D; i += blockDim.x * 4)
        *(float4*)&sm[i] = *(const float4*)&vT[i];
    __syncthreads();

    float* u = u_s + wid * ET * D;
    int gw  = blockIdx.x * nw + wid;
    int tot = gridDim.x * nw;
    int hh  = lane >> 3;

    for (int g = gw; g * ET < E; g += tot) {
        int e0 = g * ET;
        int n  = min(ET, E - e0);
        int hidx[ET];
        float eaArr[ET];

        #pragma unroll
        for (int e = 0; e < ET; e++) {
            if (e < n) {
                int t = tail[e0 + e];
                int r = etype[e0 + e] - 1;
                int h = head[e0 + e];
                hidx[e] = h;
                float4 tv = *(const float4*)&ent[(size_t)t * D + lane * 4];
                float4 rv = *(const float4*)&weight[(size_t)r * D + lane * 4];
                float4 uv = make_float4(tv.x * rv.x, tv.y * rv.y, tv.z * rv.z, tv.w * rv.w);
                *(float4*)&u[e * D + lane * 4] = uv;

                const float* Cb = &g_C[(size_t)h * (H * D) + lane * 16];
                ulonglong2 L0 = *(const ulonglong2*)&Cb[0];
                ulonglong2 L1 = *(const ulonglong2*)&Cb[4];
                ulonglong2 L2 = *(const ulonglong2*)&Cb[8];
                ulonglong2 L3 = *(const ulonglong2*)&Cb[12];
                u64 p01 = 0, p23 = 0;
                ffma2(p01, pack2(uv.x), L0.x); ffma2(p23, pack2(uv.x), L0.y);
                ffma2(p01, pack2(uv.y), L1.x); ffma2(p23, pack2(uv.y), L1.y);
                ffma2(p01, pack2(uv.z), L2.x); ffma2(p23, pack2(uv.z), L2.y);
                ffma2(p01, pack2(uv.w), L3.x); ffma2(p23, pack2(uv.w), L3.y);
                #pragma unroll
                for (int off = 16; off > 0; off >>= 1) {
                    p01 = add2(p01, __shfl_xor_sync(0xffffffffu, p01, off));
                    p23 = add2(p23, __shfl_xor_sync(0xffffffffu, p23, off));
                }
                float att = (hh == 0) ? lo2(p01) : (hh == 1) ? hi2(p01)
                          : (hh == 2) ? lo2(p23) : hi2(p23);
                att = fminf(fmaxf(att, -10.f), 10.f);
                eaArr[e] = __expf(att);
            } else {
                *(float4*)&u[e * D + lane * 4] = make_float4(0.f, 0.f, 0.f, 0.f);
            }
        }
        __syncwarp();

        u64 v01[ET], v23[ET];
        #pragma unroll
        for (int e = 0; e < ET; e++) { v01[e] = 0; v23[e] = 0; }

        #pragma unroll 2
        for (int i4 = 0; i4 < D / 4; i4++) {
            float4 uq[ET];
            #pragma unroll
            for (int e = 0; e < ET; e++) uq[e] = *(float4*)&u[e * D + i4 * 4];

            #pragma unroll
            for (int s = 0; s < 4; s++) {
                int i = i4 * 4 + s;
                ulonglong2 vv = *(ulonglong2*)&vT_s[i * D + lane * 4];
                #pragma unroll
                for (int e = 0; e < ET; e++) {
                    float us = (s == 0) ? uq[e].x : (s == 1) ? uq[e].y
                             : (s == 2) ? uq[e].z : uq[e].w;
                    u64 up = pack2(us);
                    ffma2(v01[e], up, vv.x);
                    ffma2(v23[e], up, vv.y);
                }
            }
        }

        #pragma unroll
        for (int e = 0; e < ET; e++) {
            if (e >= n) break;
            int h = hidx[e];
            float ea = eaArr[e];
            red_add_v4(&g_S[(size_t)h * D + lane * 4],
                       ea * lo2(v01[e]), ea * hi2(v01[e]),
                       ea * lo2(v23[e]), ea * hi2(v23[e]));
            if ((lane & 7) == 0)
                atomicAdd(&g_normA[(size_t)h * H + hh], ea);
        }
        __syncwarp();
    }
}

// ---------------------------------------------------------------------------
// Kernel 3 (fused finalize+N): kg = S/(normA+1e-8) computed in registers only;
// N[ent][r] = sum_i kg^2 * weight[r]^2.  8 entities per warp-iter (MLP=16);
// w2q [i4][r] float4 SMEM layout (conflict-free LDS.128); f32x2 inner loop.
// Normalized kg is never written back — only N leaves this kernel.
// ---------------------------------------------------------------------------
#define NT_EPW 8
__global__ __launch_bounds__(256) void ntable_fused_kernel(const float* __restrict__ weight,
                                                           int n_ent, int R) {
    extern __shared__ float sm[];
    float* w2q   = sm;                 // 32 i4-groups * 32 r * 4 floats = 4096 floats (16 KB)
    float* kg2_s = sm + 32 * 32 * 4;   // 8 warps * NT_EPW * D floats (32 KB)
    int tid = threadIdx.x, lane = tid & 31, wid = tid >> 5;

    for (int idx = tid; idx < 32 * 32; idx += blockDim.x) {
        int i4 = idx >> 5, r = idx & 31;
        float4 w = make_float4(0.f, 0.f, 0.f, 0.f);
        if (r < R) {
            float a = weight[r * D + i4 * 4 + 0];
            float b = weight[r * D + i4 * 4 + 1];
            float c = weight[r * D + i4 * 4 + 2];
            float d = weight[r * D + i4 * 4 + 3];
            w = make_float4(a * a, b * b, c * c, d * d);
        }
        *(float4*)&w2q[idx * 4] = w;
    }
    __syncthreads();

    float* kg2 = &kg2_s[wid * NT_EPW * D];
    int gw  = blockIdx.x * (blockDim.x >> 5) + wid;
    int tot = gridDim.x * (blockDim.x >> 5);
    int hh  = lane >> 3;

    for (int g = gw; g * NT_EPW < n_ent; g += tot) {
        int e0 = g * NT_EPW;
        int n  = min(NT_EPW, n_ent - e0);
        float4 sv[NT_EPW]; float nr[NT_EPW];
        #pragma unroll
        for (int e = 0; e < NT_EPW; e++) {
            sv[e] = make_float4(0.f, 0.f, 0.f, 0.f); nr[e] = 1.f;
            if (e < n) {
                sv[e] = *(const float4*)&g_S[(size_t)(e0 + e) * D + lane * 4];
                nr[e] = g_normA[(size_t)(e0 + e) * H + hh];
            }
        }
        #pragma unroll
        for (int e = 0; e < NT_EPW; e++) {
            float inv = 1.f / (nr[e] + 1e-8f);
            float a = sv[e].x * inv, b = sv[e].y * inv, c = sv[e].z * inv, d = sv[e].w * inv;
            *(float4*)&kg2[e * D + lane * 4] = make_float4(a * a, b * b, c * c, d * d);
        }
        __syncwarp();

        u64 acc[NT_EPW];
        #pragma unroll
        for (int e = 0; e < NT_EPW; e++) acc[e] = 0;

        #pragma unroll 4
        for (int i4 = 0; i4 < 32; i4++) {
            ulonglong2 wp = *(ulonglong2*)&w2q[(i4 * 32 + lane) * 4];
            #pragma unroll
            for (int e = 0; e < NT_EPW; e++) {
                ulonglong2 kp = *(ulonglong2*)&kg2[e * D + i4 * 4];
                ffma2(acc[e], kp.x, wp.x);
                ffma2(acc[e], kp.y, wp.y);
            }
        }
        #pragma unroll
        for (int e = 0; e < NT_EPW; e++)
            if (e < n) g_N[(size_t)(e0 + e) * R_MAX + lane] = lo2(acc[e]) + hi2(acc[e]);
        __syncwarp();
    }
}

// ---------------------------------------------------------------------------
// Kernel 4: per-edge w = N[h][r] * N[t][r]; segment max via int-atomicMax (w >= 0).
// ---------------------------------------------------------------------------
__global__ __launch_bounds__(256) void edge_w_kernel(const int* __restrict__ head,
                                                     const int* __restrict__ tail,
                                                     const int* __restrict__ etype,
                                                     int E) {
    int idx = blockIdx.x * blockDim.x + threadIdx.x;
    int tot = gridDim.x * blockDim.x;
    for (int e = idx; e < E; e += tot) {
        int h = head[e], t = tail[e], r = etype[e] - 1;
        float w = g_N[(size_t)h * R_MAX + r] * g_N[(size_t)t * R_MAX + r];
        g_w[e] = w;
        atomicMax(&g_m[h], __float_as_int(w));
    }
}

// ---------------------------------------------------------------------------
// Kernel 5: e = exp(w - m[h]);  out[h] += e * ent[tail] (RED.128);  ssum[h] += e
// ---------------------------------------------------------------------------
__global__ __launch_bounds__(256) void edge_soft_kernel(const float* __restrict__ ent,
                                                        const int* __restrict__ head,
                                                        const int* __restrict__ tail,
                                                        int E,
                                                        float* __restrict__ out) {
    int lane = threadIdx.x & 31;
    int gw   = (blockIdx.x * blockDim.x + threadIdx.x) >> 5;
    int tot  = (gridDim.x * blockDim.x) >> 5;
    for (int e = gw; e < E; e += tot) {
        int h = head[e], t = tail[e];
        float m  = __int_as_float(g_m[h]);
        float ex = __expf(g_w[e] - m);
        float4 tv = *(const float4*)&ent[(size_t)t * D + lane * 4];
        red_add_v4(&out[(size_t)h * D + lane * 4],
                   ex * tv.x, ex * tv.y, ex * tv.z, ex * tv.w);
        if (lane == 0) atomicAdd(&g_ssum[h], ex);
    }
}

// ---------------------------------------------------------------------------
// Kernel 6: out /= ssum (rows with no edges stay 0)
// ---------------------------------------------------------------------------
__global__ __launch_bounds__(256) void finalize_out_kernel(float* __restrict__ out, int n_ent) {
    int idx = blockIdx.x * blockDim.x + threadIdx.x;
    if (idx >= n_ent * (D / 4)) return;
    int row = idx >> 5;
    float s = g_ssum[row];
    float inv = (s > 0.f) ? (1.f / s) : 0.f;
    float4 o = *(float4*)&out[(size_t)idx * 4];
    o.x *= inv; o.y *= inv; o.z *= inv; o.w *= inv;
    *(float4*)&out[(size_t)idx * 4] = o;
}

// ---------------------------------------------------------------------------
extern "C" void kernel_launch(void* const* d_in, const int* in_sizes, int n_in,
                              void* d_out, int out_size) {
    const float* ent    = (const float*)d_in[0];   // [n_ent, 128]
    const float* weight = (const float*)d_in[3];   // [R, 128]
    const float* qT     = (const float*)d_in[4];   // [128, 128]
    const float* kT     = (const float*)d_in[5];
    const float* vT     = (const float*)d_in[6];
    const int*   eidx   = (const int*)d_in[7];     // [2, E]
    const int*   etype  = (const int*)d_in[8];     // [E]

    int E     = in_sizes[8];
    int n_ent = in_sizes[0] / D;
    int R     = in_sizes[3] / D;
    const int* head = eidx;
    const int* tail = eidx + E;
    float* out = (float*)d_out;

    void *pS, *pN, *pM, *pSs;
    cudaGetSymbolAddress(&pS,  g_S);
    cudaGetSymbolAddress(&pN,  g_normA);
    cudaGetSymbolAddress(&pM,  g_m);
    cudaGetSymbolAddress(&pSs, g_ssum);
    cudaMemsetAsync(pS,  0, (size_t)n_ent * D * sizeof(float));
    cudaMemsetAsync(pN,  0, (size_t)n_ent * H * sizeof(float));
    cudaMemsetAsync(pM,  0, (size_t)n_ent * sizeof(int));
    cudaMemsetAsync(pSs, 0, (size_t)n_ent * sizeof(float));
    cudaMemsetAsync(d_out, 0, (size_t)out_size * sizeof(float));

    // Kernel 1: q + C precompute (176 KB SMEM, 384 threads)
    int smem_qc = (2 * D * D + 2 * PQ_WARPS * 4 * D) * (int)sizeof(float);
    cudaFuncSetAttribute(prep_qc_kernel, cudaFuncAttributeMaxDynamicSharedMemorySize, smem_qc);
    prep_qc_kernel<<<148, PQ_THREADS, smem_qc>>>(ent, qT, kT, n_ent);

    // two no-op launches so the profiler's fixed capture slot (launch #9) lands on phase A
    noop_kernel<<<1, 32>>>();
    noop_kernel<<<1, 32>>>();

    // Kernel 2: edge phase A — 512 threads, 8 edges/warp-iter, 128 KB SMEM
    int smem_e = (D * D + (PA_THREADS / 32) * ET * D) * (int)sizeof(float);
    cudaFuncSetAttribute(edge_phaseA_kernel, cudaFuncAttributeMaxDynamicSharedMemorySize, smem_e);
    edge_phaseA_kernel<<<148, PA_THREADS, smem_e>>>(ent, weight, vT, head, tail, etype, E);

    // Kernel 3: fused normalize + N table (48 KB SMEM)
    int smem_n = (32 * 32 * 4 + 8 * NT_EPW * D) * (int)sizeof(float);
    cudaFuncSetAttribute(ntable_fused_kernel, cudaFuncAttributeMaxDynamicSharedMemorySize, smem_n);
    ntable_fused_kernel<<<512, 256, smem_n>>>(weight, n_ent, R);

    // Kernel 4 / 5
    edge_w_kernel<<<1024, 256>>>(head, tail, etype, E);
    edge_soft_kernel<<<2048, 256>>>(ent, head, tail, E, out);

    // Kernel 6
    int n3 = n_ent * (D / 4);
    finalize_out_kernel<<<(n3 + 255) / 256, 256>>>(out, n_ent);
}